// round 13
// baseline (speedup 1.0000x reference)
#include <cuda_runtime.h>

// Lag2Eul CIC deposit: x (2,4,128,128,128) f32 -> out (2,1,128,128,128) f32
// DIS_NORM = 6*512/1000 = 3.072

#define PNUM  (128*128*128)      // 2097152
#define NB    2
#define DISN  3.072f
#define RBLK  128                // partial-sum blocks per (n,dim) -> 768 blocks
#define SBLK  592                // persistent scatter blocks per batch (8/SM)

__device__ float g_part[6 * RBLK];   // overwritten every run: no zeroing needed

// grid (RBLK, 6), 256 threads. Each block:
//   - sums a contiguous 1/RBLK chunk of channel (n,c) into g_part
//   - zeroes a slice of the output (fused, rides free under the read BW)
__global__ void __launch_bounds__(256)
reduce_and_zero_kernel(const float* __restrict__ x, float* __restrict__ out) {
    int y = blockIdx.y;                 // n*3 + dim
    int n = y / 3, c = y % 3;
    const int CHUNK4 = PNUM / 4 / RBLK; // 4096 float4 per block
    const float4* base = (const float4*)(x + ((size_t)n * 4 + c) * PNUM)
                       + (size_t)blockIdx.x * CHUNK4;

    {
        const int TOT4 = NB * PNUM / 4;
        const int NBLK = RBLK * 6;      // 768
        int bid = blockIdx.y * RBLK + blockIdx.x;
        float4* o4 = (float4*)out;
        const float4 z = make_float4(0.f, 0.f, 0.f, 0.f);
        for (int i = bid * 256 + threadIdx.x; i < TOT4; i += NBLK * 256)
            o4[i] = z;
    }

    float s = 0.0f;
    #pragma unroll 4
    for (int i = threadIdx.x; i < CHUNK4; i += 256) {
        float4 v = __ldcs(&base[i]);
        s += (v.x + v.y) + (v.z + v.w);
    }
    #pragma unroll
    for (int o = 16; o > 0; o >>= 1)
        s += __shfl_down_sync(0xffffffffu, s, o);

    __shared__ float ws[8];
    if ((threadIdx.x & 31) == 0) ws[threadIdx.x >> 5] = s;
    __syncthreads();
    if (threadIdx.x < 8) {
        s = ws[threadIdx.x];
        #pragma unroll
        for (int o = 4; o > 0; o >>= 1)
            s += __shfl_down_sync(0xffu, s, o);
        if (threadIdx.x == 0) g_part[y * RBLK + blockIdx.x] = s;
    }
}

// Persistent scatter: grid (SBLK, NB), 256 threads, grid-stride over
// particle*8+corner. 8 lanes per particle, corner bits:
//   bit0 -> w offset (adjacent lanes => sector merge), bit1 -> h, bit2 -> d.
// STRIDE = SBLK*256 is divisible by 8*128, so per thread:
//   corner bits are loop-invariant, AND w = p & 127 is loop-invariant.
__global__ void __launch_bounds__(256)
scatter_kernel(const float* __restrict__ x, float* __restrict__ out) {
    int n = blockIdx.y;

    __shared__ float smean[3];
    int wid = threadIdx.x >> 5, lid = threadIdx.x & 31;
    if (wid < 3) {
        const float* gp = g_part + (n * 3 + wid) * RBLK;
        float s = gp[lid] + gp[lid + 32] + gp[lid + 64] + gp[lid + 96];
        #pragma unroll
        for (int o = 16; o > 0; o >>= 1)
            s += __shfl_down_sync(0xffffffffu, s, o);
        if (lid == 0) smean[wid] = s * (1.0f / (float)PNUM);
    }
    __syncthreads();
    const float m0 = smean[0], m1 = smean[1], m2 = smean[2];

    const float* xb = x + (size_t)n * 4 * PNUM;
    float* ob = out + (size_t)n * PNUM;
    const int TOT = PNUM * 8;            // 2^24
    const int STRIDE = SBLK * 256;       // 151552 = 8 * 128 * 148
    const int PSTR = STRIDE / 8;         // 18944, multiple of 128

    int t = blockIdx.x * 256 + threadIdx.x;
    int corner = t & 7;                  // loop-invariant
    const int cw = corner & 1;
    const int ch = (corner >> 1) & 1;
    const int cd = (corner >> 2) & 1;

    int p = t >> 3;
    const float wf = (float)(p & 127) + 0.5f;   // loop-invariant (PSTR%128==0)

    // incremented channel pointers (avoid per-iter 64-bit index math on loads)
    const float* q0 = xb + p;
    const float* q1 = xb + PNUM + p;
    const float* q2 = xb + 2 * PNUM + p;
    const float* q3 = xb + 3 * PNUM + p;

    for (; t < TOT; t += STRIDE) {
        int h = (p >> 7) & 127;
        int d = p >> 14;

        // 8 lanes share each address -> warp-broadcast loads; streaming hint
        // keeps the 64MB input from evicting the atomic-resident output in L2.
        float p0 = (__ldcs(q0) - m0) * DISN + (float)d + 0.5f;
        float p1 = (__ldcs(q1) - m1) * DISN + (float)h + 0.5f;
        float p2 = (__ldcs(q2) - m2) * DISN + wf;
        float v  =  __ldcs(q3);
        q0 += PSTR; q1 += PSTR; q2 += PSTR; q3 += PSTR;
        p  += PSTR;

        float i0 = floorf(p0), i1 = floorf(p1), i2 = floorf(p2);
        float f0 = p0 - i0, f1 = p1 - i1, f2 = p2 - i2;
        int t0 = (int)i0, t1 = (int)i1, t2 = (int)i2;

        int a0 = t0 + cd;
        int a1 = t1 + ch;
        int a2 = t2 + cw;

        float wt = (cd ? f0 : 1.0f - f0)
                 * (ch ? f1 : 1.0f - f1)
                 * (cw ? f2 : 1.0f - f2);

        if (((unsigned)a0 < 128u) & ((unsigned)a1 < 128u) &
            ((unsigned)a2 < 128u))
            atomicAdd(&ob[(a0 << 14) + (a1 << 7) + a2], v * wt);
    }
}

extern "C" void kernel_launch(void* const* d_in, const int* in_sizes, int n_in,
                              void* d_out, int out_size) {
    const float* x = (const float*)d_in[0];
    float* out = (float*)d_out;

    dim3 rgrid(RBLK, 6);
    reduce_and_zero_kernel<<<rgrid, 256>>>(x, out);

    dim3 sgrid(SBLK, NB);
    scatter_kernel<<<sgrid, 256>>>(x, out);
}

// round 14
// speedup vs baseline: 1.0432x; 1.0432x over previous
#include <cuda_runtime.h>

// Lag2Eul CIC deposit: x (2,4,128,128,128) f32 -> out (2,1,128,128,128) f32
// DIS_NORM = 6*512/1000 = 3.072
//
// Converged configuration (R12): every structural alternative falsified —
//   split REDs (R8: +130us), v2 packing (R5: +4us), f16x2 dual-mesh (R11:
//   +50us), non-148-multiple grids (R10: +8us), __ldcs/ptr-increment (R13:
//   +3.6us). Scatter sits at the L1TEX wavefront/replay floor.

#define PNUM  (128*128*128)      // 2097152
#define NB    2
#define DISN  3.072f
#define RBLK  128                // partial-sum blocks per (n,dim) -> 768 blocks
#define SBLK  592                // persistent scatter blocks per batch (8/SM)

__device__ float g_part[6 * RBLK];   // overwritten every run: no zeroing needed

// grid (RBLK, 6), 256 threads. Each block:
//   - sums a contiguous 1/RBLK chunk of channel (n,c) into g_part
//   - zeroes a slice of the output (fused, rides free under the read BW)
__global__ void __launch_bounds__(256)
reduce_and_zero_kernel(const float* __restrict__ x, float* __restrict__ out) {
    int y = blockIdx.y;                 // n*3 + dim
    int n = y / 3, c = y % 3;
    const int CHUNK4 = PNUM / 4 / RBLK; // 4096 float4 per block
    const float4* base = (const float4*)(x + ((size_t)n * 4 + c) * PNUM)
                       + (size_t)blockIdx.x * CHUNK4;

    // fused zeroing of the output: RBLK*6 blocks cover NB*PNUM floats
    {
        const int TOT4 = NB * PNUM / 4;
        const int NBLK = RBLK * 6;      // 768
        int bid = blockIdx.y * RBLK + blockIdx.x;
        float4* o4 = (float4*)out;
        const float4 z = make_float4(0.f, 0.f, 0.f, 0.f);
        for (int i = bid * 256 + threadIdx.x; i < TOT4; i += NBLK * 256)
            o4[i] = z;
    }

    float s = 0.0f;
    #pragma unroll 4
    for (int i = threadIdx.x; i < CHUNK4; i += 256) {
        float4 v = base[i];
        s += (v.x + v.y) + (v.z + v.w);
    }
    #pragma unroll
    for (int o = 16; o > 0; o >>= 1)
        s += __shfl_down_sync(0xffffffffu, s, o);

    __shared__ float ws[8];
    if ((threadIdx.x & 31) == 0) ws[threadIdx.x >> 5] = s;
    __syncthreads();
    if (threadIdx.x < 8) {
        s = ws[threadIdx.x];
        #pragma unroll
        for (int o = 4; o > 0; o >>= 1)
            s += __shfl_down_sync(0xffu, s, o);
        if (threadIdx.x == 0) g_part[y * RBLK + blockIdx.x] = s;
    }
}

// Persistent scatter: grid (SBLK, NB), 256 threads, grid-stride over
// particle*8+corner. 8 lanes per particle, corner bits:
//   bit0 -> w offset (adjacent lanes hit adjacent addresses => sector merge)
//   bit1 -> h offset, bit2 -> d offset
// One warp-wide RED.ADD.F32 covers 4 particles x 8 corners; w-pairs coalesce
// into one 32B-sector wavefront 7/8 of the time.
__global__ void __launch_bounds__(256)
scatter_kernel(const float* __restrict__ x, float* __restrict__ out) {
    int n = blockIdx.y;

    // Per-block mean finalize: warps 0-2, each lane folds 4 partials.
    __shared__ float smean[3];
    int wid = threadIdx.x >> 5, lid = threadIdx.x & 31;
    if (wid < 3) {
        const float* gp = g_part + (n * 3 + wid) * RBLK;
        float s = gp[lid] + gp[lid + 32] + gp[lid + 64] + gp[lid + 96];
        #pragma unroll
        for (int o = 16; o > 0; o >>= 1)
            s += __shfl_down_sync(0xffffffffu, s, o);
        if (lid == 0) smean[wid] = s * (1.0f / (float)PNUM);
    }
    __syncthreads();
    const float m0 = smean[0], m1 = smean[1], m2 = smean[2];

    const float* xb = x + (size_t)n * 4 * PNUM;
    float* ob = out + (size_t)n * PNUM;
    const int TOT = PNUM * 8;
    const int STRIDE = SBLK * 256;

    for (int t = blockIdx.x * 256 + threadIdx.x; t < TOT; t += STRIDE) {
        int p = t >> 3;
        int corner = t & 7;

        int w = p & 127;
        int h = (p >> 7) & 127;
        int d = p >> 14;

        // 8 lanes share each address -> warp-broadcast loads.
        float p0 = (__ldg(xb + p)            - m0) * DISN + (float)d + 0.5f;
        float p1 = (__ldg(xb + PNUM + p)     - m1) * DISN + (float)h + 0.5f;
        float p2 = (__ldg(xb + 2 * PNUM + p) - m2) * DISN + (float)w + 0.5f;
        float v  =  __ldg(xb + 3 * PNUM + p);

        float i0 = floorf(p0), i1 = floorf(p1), i2 = floorf(p2);
        float f0 = p0 - i0, f1 = p1 - i1, f2 = p2 - i2;
        int t0 = (int)i0, t1 = (int)i1, t2 = (int)i2;

        int cw = corner & 1;
        int ch = (corner >> 1) & 1;
        int cd = (corner >> 2) & 1;

        int a0 = t0 + cd;
        int a1 = t1 + ch;
        int a2 = t2 + cw;

        float wt = (cd ? f0 : 1.0f - f0)
                 * (ch ? f1 : 1.0f - f1)
                 * (cw ? f2 : 1.0f - f2);

        if (((unsigned)a0 < 128u) & ((unsigned)a1 < 128u) &
            ((unsigned)a2 < 128u))
            atomicAdd(&ob[(a0 << 14) + (a1 << 7) + a2], v * wt);
    }
}

extern "C" void kernel_launch(void* const* d_in, const int* in_sizes, int n_in,
                              void* d_out, int out_size) {
    const float* x = (const float*)d_in[0];
    float* out = (float*)d_out;

    dim3 rgrid(RBLK, 6);
    reduce_and_zero_kernel<<<rgrid, 256>>>(x, out);

    dim3 sgrid(SBLK, NB);
    scatter_kernel<<<sgrid, 256>>>(x, out);
}